// round 4
// baseline (speedup 1.0000x reference)
#include <cuda_runtime.h>

#define BATCH   16
#define CIN     64
#define HW      64
#define OC      128
#define NLEAF   16
#define NGATE   15

// Spatial y-tile per CTA: 32 wide x 8 tall. Halo for taps (py,px in [0,2], pad 1):
// x rows [r0-1, r0+8] (10 rows), x cols [c0-1, c0+32] (34 cols).
#define TW 32
#define TH 8
#define SC 34
#define SR 10
#define CH_STRIDE (SR * SC)            // 340
#define SMEM_ELEMS (CIN * CH_STRIDE)   // 21760
#define SMEM_BYTES (SMEM_ELEMS * 4)    // 87040

// Precomputed per-launch (deterministic function of inputs; recomputed every replay).
__device__ float g_coef[OC * NGATE * 4];
__device__ int   g_off[OC * NLEAF];

__device__ __constant__ float OP2POLY[16][4] = {
    {0, 0, 0, 0}, {0, 0, 0, 1}, {0, 1, 0, -1}, {0, 1, 0, 0},
    {0, 0, 1, -1}, {0, 0, 1, 0}, {0, 1, 1, -2}, {0, 1, 1, -1},
    {1, -1, -1, 1}, {1, -1, -1, 2}, {1, 0, -1, 0}, {1, 0, -1, 1},
    {1, -1, 0, 0}, {1, -1, 0, 1}, {1, 0, 0, -1}, {1, 0, 0, 0}
};

// Tiny prep: argmax over 16 ops -> 4 poly coeffs per gate; fold (ci,py,px) into a
// single smem element offset per leaf.
__global__ void prep_kernel(const float* __restrict__ w,
                            const int* __restrict__ ci,
                            const int* __restrict__ px,
                            const int* __restrict__ py) {
    int tid = blockIdx.x * blockDim.x + threadIdx.x;
    if (tid < OC * NGATE) {
        const float* wp = w + tid * 16;
        float best = wp[0];
        int bi = 0;
#pragma unroll
        for (int k = 1; k < 16; k++) {
            float v = wp[k];
            if (v > best) { best = v; bi = k; }  // first-max tiebreak == jnp.argmax
        }
#pragma unroll
        for (int c = 0; c < 4; c++) g_coef[tid * 4 + c] = OP2POLY[bi][c];
    }
    if (tid < OC * NLEAF) {
        g_off[tid] = ci[tid] * CH_STRIDE + py[tid] * SC + px[tid];
    }
}

__device__ __forceinline__ float gate_eval(const float* c, float a, float b) {
    float r = fmaf(c[3], a * b, c[0]);
    r = fmaf(c[1], a, r);
    r = fmaf(c[2], b, r);
    return r;
}

__global__ void __launch_bounds__(256, 2)
logic_tree_kernel(const float* __restrict__ x, float* __restrict__ out) {
    extern __shared__ float sm[];

    const int tile = blockIdx.x;        // 0..15: tx in [0,2), ty in [0,8)
    const int b    = blockIdx.y;        // 0..15
    const int tx   = tile & 1;
    const int ty   = tile >> 1;
    const int r0   = ty * TH;
    const int c0   = tx * TW;
    const int tid  = threadIdx.x;

    // Stage all 64 channels of the halo region into smem (coalesced-ish, zero-fill OOB).
    const float* xb = x + (size_t)b * CIN * HW * HW;
    for (int idx = tid; idx < SMEM_ELEMS; idx += 256) {
        int c   = idx / CH_STRIDE;
        int rem = idx - c * CH_STRIDE;
        int r   = rem / SC;
        int col = rem - r * SC;
        int gr  = r0 - 1 + r;
        int gc  = c0 - 1 + col;
        float v = 0.0f;
        if ((unsigned)gr < HW && (unsigned)gc < HW)
            v = xb[(c * HW + gr) * HW + gc];
        sm[idx] = v;
    }
    __syncthreads();

    const int w    = tid >> 5;   // warp 0..7
    const int lane = tid & 31;   // y-column within tile -> conflict-free LDS

    for (int oc = w; oc < OC; oc += 8) {
        int off[NLEAF];
#pragma unroll
        for (int n = 0; n < NLEAF; n++) off[n] = g_off[oc * NLEAF + n];

        float cf[NGATE * 4];
#pragma unroll
        for (int k = 0; k < NGATE * 4; k++) cf[k] = g_coef[oc * NGATE * 4 + k];

        float* outoc = out + (((size_t)b * OC + oc) * 32 + ty * 4) * 32 + tx * 16;

#pragma unroll
        for (int ph = 0; ph < 4; ph++) {
            float prodp = 1.0f;
#pragma unroll
            for (int sub = 0; sub < 2; sub++) {
                const int base = (ph * 2 + sub) * SC + lane;

                float v[16];
#pragma unroll
                for (int n = 0; n < 16; n++) v[n] = sm[off[n] + base];

                float u[8];
#pragma unroll
                for (int n = 0; n < 8; n++)
                    u[n] = gate_eval(&cf[n * 4], v[2 * n], v[2 * n + 1]);

                float t[4];
#pragma unroll
                for (int n = 0; n < 4; n++)
                    t[n] = gate_eval(&cf[(8 + n) * 4], u[2 * n], u[2 * n + 1]);

                float s0 = gate_eval(&cf[12 * 4], t[0], t[1]);
                float s1 = gate_eval(&cf[13 * 4], t[2], t[3]);
                float y  = gate_eval(&cf[14 * 4], s0, s1);

                prodp *= (1.0f - y);
            }
            // Column pooling: combine neighbor lane (j even/odd pair).
            float other = __shfl_xor_sync(0xffffffffu, prodp, 1);
            if ((lane & 1) == 0) {
                outoc[ph * 32 + (lane >> 1)] = 1.0f - prodp * other;
            }
        }
    }
}

extern "C" void kernel_launch(void* const* d_in, const int* in_sizes, int n_in,
                              void* d_out, int out_size) {
    const float* x   = (const float*)d_in[0];
    const float* wts = (const float*)d_in[1];
    const int*   ci  = (const int*)d_in[2];
    const int*   px  = (const int*)d_in[3];
    const int*   py  = (const int*)d_in[4];
    float*       out = (float*)d_out;

    cudaFuncSetAttribute(logic_tree_kernel,
                         cudaFuncAttributeMaxDynamicSharedMemorySize, SMEM_BYTES);

    prep_kernel<<<16, 256>>>(wts, ci, px, py);

    dim3 grid(16, BATCH);   // 16 spatial tiles x 16 batches = 256 CTAs (one wave at occ 2)
    logic_tree_kernel<<<grid, 256, SMEM_BYTES>>>(x, out);
}